// round 10
// baseline (speedup 1.0000x reference)
#include <cuda_runtime.h>
#include <math.h>

#define NQ 16
#define DIM 65536
#define BATCH 64
#define NC 23

// State layout (per sample, 65536 float2): addr(j) = j0 | (j[4..15]<<1) | (j[1..3]<<13)
__device__ float4 g_state4[BATCH * DIM / 2];   // 32 MB
__device__ float2 g_U[2][BATCH][NQ][4];        // fused Rot@RX per layer/sample/wire
__device__ float2 g_crx[2][NQ];                // (cos(th/2), sin(th/2))
__device__ float  g_partial[BATCH][8][16];

#define PD(i) ((i) + ((i) >> 4))
#define SMEM_F2 8704
#define SMEM_BYTES (SMEM_F2 * 8)

__device__ __forceinline__ float2 cmul(float2 a, float2 b) {
    return make_float2(a.x * b.x - a.y * b.y, a.x * b.y + a.y * b.x);
}
__device__ __forceinline__ void umix(float2& a0, float2& a1,
                                     float2 u0, float2 u1, float2 u2, float2 u3) {
    float2 n0, n1;
    n0.x = u0.x * a0.x - u0.y * a0.y + u1.x * a1.x - u1.y * a1.y;
    n0.y = u0.x * a0.y + u0.y * a0.x + u1.x * a1.y + u1.y * a1.x;
    n1.x = u2.x * a0.x - u2.y * a0.y + u3.x * a1.x - u3.y * a1.y;
    n1.y = u2.x * a0.y + u2.y * a0.x + u3.x * a1.y + u3.y * a1.x;
    a0 = n0; a1 = n1;
}
// RX pair mix applied under control=1: RX=[[c,-is],[-is,c]]
__device__ __forceinline__ void crxmix(float2& a0, float2& a1, float c, float s) {
    float2 n0 = make_float2(c * a0.x + s * a1.y, c * a0.y - s * a1.x);
    float2 n1 = make_float2(s * a0.y + c * a1.x, -s * a0.x + c * a1.y);
    a0 = n0; a1 = n1;
}
// apply U to the 4 pairs across window bit K of an 8-amp register window
template<int K>
__device__ __forceinline__ void applyU8(float2* r, const float2* __restrict__ gu) {
    float2 u0 = gu[0], u1 = gu[1], u2 = gu[2], u3 = gu[3];
    #pragma unroll
    for (int j = 0; j < 8; j++)
        if (!((j >> K) & 1))
            umix(r[j], r[j | (1 << K)], u0, u1, u2, u3);
}

// ---------------- P0: fused U = Rot @ RX, CRX tables ------------------------
__global__ void k_prep(const float* __restrict__ x, const float* __restrict__ w0,
                       const float* __restrict__ x0, const float* __restrict__ w1,
                       const float* __restrict__ x1) {
    int t = blockIdx.x * blockDim.x + threadIdx.x;
    if (t < 2 * NQ) {
        int l = t >> 4, q = t & 15;
        float th = 0.5f * (l == 0 ? x0[q] : x1[q]);
        g_crx[l][q] = make_float2(cosf(th), sinf(th));
    }
    if (t < 2 * BATCH * NQ) {
        int l = t / (BATCH * NQ);
        int r = t % (BATCH * NQ);
        int b = r / NQ, q = r % NQ;
        float hx = 0.5f * x[b * NQ + q];
        float cx = cosf(hx), sx = sinf(hx);
        const float* w = (l == 0 ? w0 : w1) + q * 3;
        float phi = w[0], th = w[1], om = w[2];
        float ct = cosf(0.5f * th), st = sinf(0.5f * th);
        float ap = 0.5f * (phi + om), am = 0.5f * (phi - om);
        float cap = cosf(ap), sap = sinf(ap), cam = cosf(am), sam = sinf(am);
        float2 a  = make_float2(cap * ct, -sap * ct);
        float2 bb = make_float2(-cam * st, -sam * st);
        float2 cc = make_float2(cam * st, -sam * st);
        float2 d  = make_float2(cap * ct,  sap * ct);
        g_U[l][b][q][0] = make_float2(a.x * cx + bb.y * sx,  a.y * cx - bb.x * sx);
        g_U[l][b][q][1] = make_float2(a.y * sx + bb.x * cx, -a.x * sx + bb.y * cx);
        g_U[l][b][q][2] = make_float2(cc.x * cx + d.y * sx,  cc.y * cx - d.x * sx);
        g_U[l][b][q][3] = make_float2(cc.y * sx + d.x * cx, -cc.x * sx + d.y * cx);
    }
}

// ---- chain0 3-bit window at shift SH (contiguous local bits SH..SH+2) -------
// order: [cond RX q2 on w2 (first window, ctrl=j13 chunk bit)], L1 CRX q=13-SH
// (w2->w1), L1 CRX q=14-SH (w1->w0), L2 U wire 13-SH @w2, L2 U wire 14-SH @w1.
template<int SH, bool FIRST>
__device__ __forceinline__ void cwin(float2* s, int v, int b, bool doq2) {
    int base = ((v >> SH) << (SH + 3)) | (v & ((1 << SH) - 1));
    float2 r[8];
    #pragma unroll
    for (int i = 0; i < 8; i++) r[i] = s[PD(base + (i << SH))];
    if (FIRST && doq2) {
        float2 cs = g_crx[0][2];
        crxmix(r[0], r[4], cs.x, cs.y); crxmix(r[1], r[5], cs.x, cs.y);
        crxmix(r[2], r[6], cs.x, cs.y); crxmix(r[3], r[7], cs.x, cs.y);
    }
    {   float2 cs = g_crx[0][13 - SH];                // ctrl w2 -> tgt w1
        crxmix(r[4], r[6], cs.x, cs.y); crxmix(r[5], r[7], cs.x, cs.y); }
    {   float2 cs = g_crx[0][14 - SH];                // ctrl w1 -> tgt w0
        crxmix(r[2], r[3], cs.x, cs.y); crxmix(r[6], r[7], cs.x, cs.y); }
    applyU8<2>(r, &g_U[1][b][13 - SH][0]);            // U @ bit SH+2
    applyU8<1>(r, &g_U[1][b][14 - SH][0]);            // U @ bit SH+1
    #pragma unroll
    for (int i = 0; i < 8; i++) s[PD(base + (i << SH))] = r[i];
}

// ---- mid 3-bit chain window at shift SH: L2 CRX q=10-SH (w2->w1), q=11-SH ---
template<int SH>
__device__ __forceinline__ void mwin(float2* s, int v) {
    int base = ((v >> SH) << (SH + 3)) | (v & ((1 << SH) - 1));
    float2 r[8];
    #pragma unroll
    for (int i = 0; i < 8; i++) r[i] = s[PD(base + (i << SH))];
    {   float2 cs = g_crx[1][10 - SH];
        crxmix(r[4], r[6], cs.x, cs.y); crxmix(r[5], r[7], cs.x, cs.y); }
    {   float2 cs = g_crx[1][11 - SH];
        crxmix(r[2], r[3], cs.x, cs.y); crxmix(r[6], r[7], cs.x, cs.y); }
    #pragma unroll
    for (int i = 0; i < 8; i++) s[PD(base + (i << SH))] = r[i];
}

// ------- P1: chain0 — generate product state (L1 all-U + q0,q1) in smem,
//         apply L1 q2(cond)..q14 + L2 U wires 3..14 via 6 window passes,
//         store permuted layout.  Block owns j bits 0..12; chunk = j[13..15].
__global__ __launch_bounds__(512, 2) void k_chain0() {
    extern __shared__ float2 s[];
    __shared__ float2 A[256], Bv[32], f[16][2];
    int b = blockIdx.y, tid = threadIdx.x, chunk = blockIdx.x;
    if (tid < 32) f[tid >> 1][tid & 1] = g_U[0][b][15 - (tid >> 1)][(tid & 1) * 2];
    __syncthreads();
    if (tid < 256) {   // A: product over bits 0..7
        float2 c = f[0][tid & 1];
        #pragma unroll
        for (int j = 1; j <= 7; j++) c = cmul(c, f[j][(tid >> j) & 1]);
        A[tid] = c;
    }
    if (tid < 32) {
        float2 c = f[8][tid & 1];
        #pragma unroll
        for (int j = 9; j <= 12; j++) c = cmul(c, f[j][(tid >> (j - 8)) & 1]);
        float2 F[8];
        #pragma unroll
        for (int i = 0; i < 8; i++)
            F[i] = cmul(cmul(f[13][i & 1], f[14][(i >> 1) & 1]), f[15][(i >> 2) & 1]);
        float2 cs = g_crx[0][0];                      // q0: ctrl b15 -> tgt b14
        crxmix(F[4], F[6], cs.x, cs.y); crxmix(F[5], F[7], cs.x, cs.y);
        cs = g_crx[0][1];                             // q1: ctrl b14 -> tgt b13
        crxmix(F[2], F[3], cs.x, cs.y); crxmix(F[6], F[7], cs.x, cs.y);
        Bv[tid] = cmul(c, F[chunk]);
    }
    __syncthreads();
    #pragma unroll
    for (int k = 0; k < 16; k++) {
        int j = tid + (k << 9);
        s[PD(j)] = cmul(A[j & 255], Bv[j >> 8]);
    }
    __syncthreads();
    bool doq2 = (chunk & 1);                          // j13 == 1
    cwin<10, true>(s, tid, b, doq2); cwin<10, true>(s, tid + 512, b, doq2); __syncthreads();
    cwin<8, false>(s, tid, b, false); cwin<8, false>(s, tid + 512, b, false); __syncthreads();
    cwin<6, false>(s, tid, b, false); cwin<6, false>(s, tid + 512, b, false); __syncthreads();
    cwin<4, false>(s, tid, b, false); cwin<4, false>(s, tid + 512, b, false); __syncthreads();
    cwin<2, false>(s, tid, b, false); cwin<2, false>(s, tid + 512, b, false); __syncthreads();
    cwin<0, false>(s, tid, b, false); cwin<0, false>(s, tid + 512, b, false); __syncthreads();
    // store, permuted: f4 idx = (p>>3) | (chunk<<9) | ((p&7)<<12)
    float4* g4 = g_state4 + (size_t)b * 32768;
    #pragma unroll
    for (int k = 0; k < 8; k++) {
        int p = tid + (k << 9);
        float2 lo = s[PD(2 * p)], hi = s[PD(2 * p + 1)];
        g4[(p >> 3) | (chunk << 9) | ((p & 7) << 12)] = make_float4(lo.x, lo.y, hi.x, hi.y);
    }
}

// ------- P2: k_mid — owns j bits {0,4..15}; chunk = j[1..3] (contiguous 64KB).
// Gates: L1 wrap q15; L2 U wires 0,1,2,15; L2 CRX q0..q10.
// Local l: l0=j0, l[1..12]=j[4..15]  (j15=l12, j14=l11, j13=l10, j12=l9, ...)
__global__ __launch_bounds__(512, 2) void k_mid() {
    extern __shared__ float2 s[];
    int b = blockIdx.y, cc = blockIdx.x, tid = threadIdx.x;
    float4* g4 = g_state4 + (size_t)b * 32768 + ((size_t)cc << 12);
    #pragma unroll
    for (int k = 0; k < 8; k++) {
        int q = tid + (k << 9);
        float4 v = g4[q];
        s[PD(2 * q)]     = make_float2(v.x, v.y);
        s[PD(2 * q + 1)] = make_float2(v.z, v.w);
    }
    __syncthreads();
    // W_A: bits (w2,w1,w0) = (l12,l11,l0) = (j15,j14,j0); free bits l1..l10.
    #pragma unroll
    for (int k = 0; k < 2; k++) {
        int v = tid + (k << 9);
        int base = v << 1;
        float2 r[8];
        #pragma unroll
        for (int i = 0; i < 8; i++) {
            int o = (i & 1) | (((i >> 1) & 1) << 11) | (((i >> 2) & 1) << 12);
            r[i] = s[PD(base + o)];
        }
        {   // L1 wrap q15: ctrl j0 (w0) -> tgt j15 (w2)
            float2 cs = g_crx[0][15];
            crxmix(r[1], r[5], cs.x, cs.y); crxmix(r[3], r[7], cs.x, cs.y);
        }
        applyU8<2>(r, &g_U[1][b][0][0]);              // U wire0  @ j15
        applyU8<1>(r, &g_U[1][b][1][0]);              // U wire1  @ j14
        applyU8<0>(r, &g_U[1][b][15][0]);             // U wire15 @ j0
        {   // L2 q0: ctrl j15 (w2) -> tgt j14 (w1)
            float2 cs = g_crx[1][0];
            crxmix(r[4], r[6], cs.x, cs.y); crxmix(r[5], r[7], cs.x, cs.y);
        }
        #pragma unroll
        for (int i = 0; i < 8; i++) {
            int o = (i & 1) | (((i >> 1) & 1) << 11) | (((i >> 2) & 1) << 12);
            s[PD(base + o)] = r[i];
        }
    }
    __syncthreads();
    // W_B: bits l{11,10,9} = j{14,13,12}: U wire2 @ j13 (w1), q1 (w2->w1), q2 (w1->w0)
    #pragma unroll
    for (int k = 0; k < 2; k++) {
        int v = tid + (k << 9);
        int base = ((v >> 9) << 12) | (v & 511);
        float2 r[8];
        #pragma unroll
        for (int i = 0; i < 8; i++) r[i] = s[PD(base + (i << 9))];
        applyU8<1>(r, &g_U[1][b][2][0]);
        {   float2 cs = g_crx[1][1];
            crxmix(r[4], r[6], cs.x, cs.y); crxmix(r[5], r[7], cs.x, cs.y); }
        {   float2 cs = g_crx[1][2];
            crxmix(r[2], r[3], cs.x, cs.y); crxmix(r[6], r[7], cs.x, cs.y); }
        #pragma unroll
        for (int i = 0; i < 8; i++) s[PD(base + (i << 9))] = r[i];
    }
    __syncthreads();
    mwin<7>(s, tid); mwin<7>(s, tid + 512); __syncthreads();   // q3,q4
    mwin<5>(s, tid); mwin<5>(s, tid + 512); __syncthreads();   // q5,q6
    mwin<3>(s, tid); mwin<3>(s, tid + 512); __syncthreads();   // q7,q8
    mwin<1>(s, tid); mwin<1>(s, tid + 512); __syncthreads();   // q9,q10
    #pragma unroll
    for (int k = 0; k < 8; k++) {
        int q = tid + (k << 9);
        float2 lo = s[PD(2 * q)], hi = s[PD(2 * q + 1)];
        g4[q] = make_float4(lo.x, lo.y, hi.x, hi.y);
    }
}

// ------- P3: k_measure2 — owns j bits {0..11,15}; chunk cb = j[12..14].
// L2 q11..q13 (smem window), then q14,q15 fused into signed |amp|^2 reduce.
// Local m: m0=j0, m[1..8]=j[4..11], m9=j15, m10..m12=j[1..3].
__global__ __launch_bounds__(512) void k_measure2() {
    extern __shared__ float2 s[];
    int b = blockIdx.y, cb = blockIdx.x, tid = threadIdx.x;
    int tl = tid & 255, th = tid >> 8;
    const float4* g4 = g_state4 + (size_t)b * 32768;
    #pragma unroll
    for (int k = 0; k < 8; k++) {
        int t = (k << 1) | th;
        float4 v = g4[(t << 11) | (cb << 8) | tl];
        int m = (t << 9) | (tl << 1);
        s[PD(m)]     = make_float2(v.x, v.y);
        s[PD(m + 1)] = make_float2(v.z, v.w);
    }
    __syncthreads();
    // V1: window m{10,11,12,1}: (w3,w2,w1,w0)=(j4,j3,j2,j1): q11,q12,q13
    {
        int v = tid;
        int base = (v & 1) | ((v >> 1) << 2);         // free m bits {0,2..9}
        float2 r[16];
        #pragma unroll
        for (int i = 0; i < 16; i++) {
            int o = ((i & 1) << 10) | (((i >> 1) & 1) << 11) | (((i >> 2) & 1) << 12) | (((i >> 3) & 1) << 1);
            r[i] = s[PD(base + o)];
        }
        {   float2 cs = g_crx[1][11];
            #pragma unroll
            for (int j = 0; j < 16; j++)
                if (((j >> 3) & 1) && !((j >> 2) & 1)) crxmix(r[j], r[j | 4], cs.x, cs.y); }
        {   float2 cs = g_crx[1][12];
            #pragma unroll
            for (int j = 0; j < 16; j++)
                if (((j >> 2) & 1) && !((j >> 1) & 1)) crxmix(r[j], r[j | 2], cs.x, cs.y); }
        {   float2 cs = g_crx[1][13];
            #pragma unroll
            for (int j = 0; j < 16; j++)
                if (((j >> 1) & 1) && !(j & 1)) crxmix(r[j], r[j | 1], cs.x, cs.y); }
        #pragma unroll
        for (int i = 0; i < 16; i++) {
            int o = ((i & 1) << 10) | (((i >> 1) & 1) << 11) | (((i >> 2) & 1) << 12) | (((i >> 3) & 1) << 1);
            s[PD(base + o)] = r[i];
        }
    }
    __syncthreads();
    // V2: window m{0,10,9}: (w2,w1,w0)=(j15,j1,j0): q14, q15 + reduce
    float sums[16];
    #pragma unroll
    for (int w = 0; w < 16; w++) sums[w] = 0.f;
    float Tsum = 0.f;
    float2 c14 = g_crx[1][14], c15 = g_crx[1][15];
    #pragma unroll
    for (int k = 0; k < 2; k++) {
        int v = tid + (k << 9);                       // 0..1023
        int base = ((v & 255) << 1) | ((v >> 8) << 11);  // free m bits {1..8,11,12}
        float2 r[8];
        #pragma unroll
        for (int i = 0; i < 8; i++) {
            int o = (i & 1) | (((i >> 1) & 1) << 10) | (((i >> 2) & 1) << 9);
            r[i] = s[PD(base + o)];
        }
        // q14: ctrl j1 (w1) -> tgt j0 (w0)
        crxmix(r[2], r[3], c14.x, c14.y); crxmix(r[6], r[7], c14.x, c14.y);
        // q15: ctrl j0 (w0) -> tgt j15 (w2)
        crxmix(r[1], r[5], c15.x, c15.y); crxmix(r[3], r[7], c15.x, c15.y);
        float p[8];
        #pragma unroll
        for (int i = 0; i < 8; i++) p[i] = r[i].x * r[i].x + r[i].y * r[i].y;
        float T = p[0] + p[1] + p[2] + p[3] + p[4] + p[5] + p[6] + p[7];
        float Aw2 = p[4] + p[5] + p[6] + p[7];        // j15=1
        float Bw0 = p[1] + p[3] + p[5] + p[7];        // j0=1
        float Cw1 = p[2] + p[3] + p[6] + p[7];        // j1=1
        sums[0]  += T - 2.f * Aw2;                    // wire0  <- j15
        sums[15] += T - 2.f * Bw0;                    // wire15 <- j0
        sums[14] += T - 2.f * Cw1;                    // wire14 <- j1
        Tsum += T;
        #pragma unroll
        for (int w = 4; w <= 11; w++)                 // wire w <- m(12-w) = j(15-w)
            sums[w] += ((base >> (12 - w)) & 1) ? -T : T;
        sums[12] += ((base >> 12) & 1) ? -T : T;      // wire12 <- j3 (m12)
        sums[13] += ((base >> 11) & 1) ? -T : T;      // wire13 <- j2 (m11)
    }
    sums[1] = ((cb >> 2) & 1) ? -Tsum : Tsum;         // wire1 <- j14
    sums[2] = ((cb >> 1) & 1) ? -Tsum : Tsum;         // wire2 <- j13
    sums[3] = (cb & 1) ? -Tsum : Tsum;                // wire3 <- j12
    __syncthreads();
    float* sf = (float*)s;                            // [512][17] padded
    #pragma unroll
    for (int w = 0; w < 16; w++) sf[tid * 17 + w] = sums[w];
    __syncthreads();
    int wid = tid >> 5, lane = tid & 31;              // warp wid handles wire wid
    if (wid < 16) {
        float v = 0.f;
        #pragma unroll
        for (int k = 0; k < 16; k++) v += sf[(lane + (k << 5)) * 17 + wid];
        #pragma unroll
        for (int o = 16; o; o >>= 1) v += __shfl_xor_sync(0xffffffffu, v, o);
        if (lane == 0) g_partial[b][cb][wid] = v;
    }
}

// ---------------- P4: FC + log_softmax --------------------------------------
__global__ void k_head(const float* __restrict__ fc_w, const float* __restrict__ fc_b,
                       float* __restrict__ out) {
    int b = blockIdx.x, lane = threadIdx.x;
    __shared__ float feats[16];
    if (lane < 16) {
        float v = 0.f;
        #pragma unroll
        for (int k = 0; k < 8; k++) v += g_partial[b][k][lane];
        feats[lane] = v;
    }
    __syncthreads();
    float logit = -1e30f;
    if (lane < NC) {
        float v = fc_b[lane];
        #pragma unroll
        for (int w = 0; w < 16; w++) v += feats[w] * fc_w[lane * 16 + w];
        logit = v;
    }
    float m = logit;
    #pragma unroll
    for (int o = 16; o; o >>= 1) m = fmaxf(m, __shfl_xor_sync(0xffffffffu, m, o));
    float e = (lane < NC) ? expf(logit - m) : 0.f;
    #pragma unroll
    for (int o = 16; o; o >>= 1) e += __shfl_xor_sync(0xffffffffu, e, o);
    float lse = m + logf(e);
    if (lane < NC) out[b * NC + lane] = logit - lse;
}

extern "C" void kernel_launch(void* const* d_in, const int* in_sizes, int n_in,
                              void* d_out, int out_size) {
    const float* x    = (const float*)d_in[0];
    const float* w0   = (const float*)d_in[1];
    const float* x0   = (const float*)d_in[2];
    const float* w1   = (const float*)d_in[3];
    const float* x1   = (const float*)d_in[4];
    const float* fc_w = (const float*)d_in[5];
    const float* fc_b = (const float*)d_in[6];
    float* out = (float*)d_out;

    cudaFuncSetAttribute(k_chain0,   cudaFuncAttributeMaxDynamicSharedMemorySize, SMEM_BYTES);
    cudaFuncSetAttribute(k_mid,      cudaFuncAttributeMaxDynamicSharedMemorySize, SMEM_BYTES);
    cudaFuncSetAttribute(k_measure2, cudaFuncAttributeMaxDynamicSharedMemorySize, SMEM_BYTES);

    k_prep<<<8, 256>>>(x, w0, x0, w1, x1);
    k_chain0<<<dim3(8, BATCH), 512, SMEM_BYTES>>>();
    k_mid<<<dim3(8, BATCH), 512, SMEM_BYTES>>>();
    k_measure2<<<dim3(8, BATCH), 512, SMEM_BYTES>>>();
    k_head<<<BATCH, 32>>>(fc_w, fc_b, out);
}

// round 11
// speedup vs baseline: 1.9855x; 1.9855x over previous
#include <cuda_runtime.h>
#include <math.h>

#define NQ 16
#define DIM 65536
#define BATCH 64
#define NC 23

__device__ float4 g_state4[BATCH * DIM / 2];   // 32 MB state, normal layout
__device__ float2 g_U[2][BATCH][NQ][4];        // fused Rot@RX per layer/sample/wire
__device__ float2 g_crx[2][NQ];                // (cos(th/2), sin(th/2))
__device__ float  g_partial[BATCH][8][16];

#define PD(i) ((i) + ((i) >> 4))
#define SMEM_F2 8704
#define SMEM_BYTES (SMEM_F2 * 8)

__device__ __forceinline__ float2 cmul(float2 a, float2 b) {
    return make_float2(a.x * b.x - a.y * b.y, a.x * b.y + a.y * b.x);
}
__device__ __forceinline__ void umix(float2& a0, float2& a1,
                                     float2 u0, float2 u1, float2 u2, float2 u3) {
    float2 n0, n1;
    n0.x = u0.x * a0.x - u0.y * a0.y + u1.x * a1.x - u1.y * a1.y;
    n0.y = u0.x * a0.y + u0.y * a0.x + u1.x * a1.y + u1.y * a1.x;
    n1.x = u2.x * a0.x - u2.y * a0.y + u3.x * a1.x - u3.y * a1.y;
    n1.y = u2.x * a0.y + u2.y * a0.x + u3.x * a1.y + u3.y * a1.x;
    a0 = n0; a1 = n1;
}
// RX pair mix applied under control=1: RX=[[c,-is],[-is,c]]
__device__ __forceinline__ void crxmix(float2& a0, float2& a1, float c, float s) {
    float2 n0 = make_float2(c * a0.x + s * a1.y, c * a0.y - s * a1.x);
    float2 n1 = make_float2(s * a0.y + c * a1.x, -s * a0.x + c * a1.y);
    a0 = n0; a1 = n1;
}

// ---------------- P0: fused U = Rot @ RX, CRX tables ------------------------
__global__ void k_prep(const float* __restrict__ x, const float* __restrict__ w0,
                       const float* __restrict__ x0, const float* __restrict__ w1,
                       const float* __restrict__ x1) {
    int t = blockIdx.x * blockDim.x + threadIdx.x;
    if (t < 2 * NQ) {
        int l = t >> 4, q = t & 15;
        float th = 0.5f * (l == 0 ? x0[q] : x1[q]);
        g_crx[l][q] = make_float2(cosf(th), sinf(th));
    }
    if (t < 2 * BATCH * NQ) {
        int l = t / (BATCH * NQ);
        int r = t % (BATCH * NQ);
        int b = r / NQ, q = r % NQ;
        float hx = 0.5f * x[b * NQ + q];
        float cx = cosf(hx), sx = sinf(hx);
        const float* w = (l == 0 ? w0 : w1) + q * 3;
        float phi = w[0], th = w[1], om = w[2];
        float ct = cosf(0.5f * th), st = sinf(0.5f * th);
        float ap = 0.5f * (phi + om), am = 0.5f * (phi - om);
        float cap = cosf(ap), sap = sinf(ap), cam = cosf(am), sam = sinf(am);
        float2 a  = make_float2(cap * ct, -sap * ct);
        float2 bb = make_float2(-cam * st, -sam * st);
        float2 cc = make_float2(cam * st, -sam * st);
        float2 d  = make_float2(cap * ct,  sap * ct);
        g_U[l][b][q][0] = make_float2(a.x * cx + bb.y * sx,  a.y * cx - bb.x * sx);
        g_U[l][b][q][1] = make_float2(a.y * sx + bb.x * cx, -a.x * sx + bb.y * cx);
        g_U[l][b][q][2] = make_float2(cc.x * cx + d.y * sx,  cc.y * cx - d.x * sx);
        g_U[l][b][q][3] = make_float2(cc.y * sx + d.x * cx, -cc.x * sx + d.y * cx);
    }
}

// ---------------- generic window gate helpers --------------------------------
template<int H, int L>
__device__ __forceinline__ void applyCRX(float2* r, float2 cs) {
    #pragma unroll
    for (int j = 0; j < 16; j++)
        if (((j >> H) & 1) && !((j >> L) & 1))
            crxmix(r[j], r[j | (1 << L)], cs.x, cs.y);
}
template<int K>
__device__ __forceinline__ void applyU(float2* r, const float2* __restrict__ gu) {
    float2 u0 = gu[0], u1 = gu[1], u2 = gu[2], u3 = gu[3];
    #pragma unroll
    for (int j = 0; j < 16; j++)
        if (!((j >> K) & 1))
            umix(r[j], r[j | (1 << K)], u0, u1, u2, u3);
}

// contiguous 4-bit window over local bits [sh, sh+3]; applies CRX q, q+1, q+2
// (layer lr); optionally 3 U wires (layer 2) and a leading conditional RX.
__device__ __forceinline__ void window_chain(float2* s, int v, int sh, int lr, int q,
                                             const float2* uw0, const float2* uw1,
                                             const float2* uw2, bool dopre, int preq) {
    int low  = v & ((1 << sh) - 1);
    int base = ((v >> sh) << (sh + 4)) | low;
    float2 r[16];
    #pragma unroll
    for (int j = 0; j < 16; j++) r[j] = s[PD(base + (j << sh))];
    if (dopre) {                                      // uncontrolled RX on window bit 3
        float2 cs = g_crx[lr][preq];
        #pragma unroll
        for (int j = 0; j < 8; j++) crxmix(r[j], r[j | 8], cs.x, cs.y);
    }
    applyCRX<3, 2>(r, g_crx[lr][q]);
    applyCRX<2, 1>(r, g_crx[lr][q + 1]);
    applyCRX<1, 0>(r, g_crx[lr][q + 2]);
    if (uw0) {
        applyU<3>(r, uw0);
        applyU<2>(r, uw1);
        applyU<1>(r, uw2);
    }
    #pragma unroll
    for (int j = 0; j < 16; j++) s[PD(base + (j << sh))] = r[j];
}

// ------- P1: chain0 — generate product state (L1 all-U + q0,q1) in smem,
//         apply L1 q2(cond)..q14 + L2 U wires 3..14, store normal layout.
//         Block owns j bits 0..12; chunk = j[13..15].
__global__ __launch_bounds__(256) void k_chain0() {
    extern __shared__ float2 s[];
    __shared__ float2 A[256], Bv[32], f[16][2];
    int b = blockIdx.y, tid = threadIdx.x, chunk = blockIdx.x;
    if (tid < 32) f[tid >> 1][tid & 1] = g_U[0][b][15 - (tid >> 1)][(tid & 1) * 2];
    __syncthreads();
    {   // A: product over bits 0..7
        float2 c = f[0][tid & 1];
        #pragma unroll
        for (int j = 1; j <= 7; j++) c = cmul(c, f[j][(tid >> j) & 1]);
        A[tid] = c;
    }
    if (tid < 32) {
        float2 c = f[8][tid & 1];
        #pragma unroll
        for (int j = 9; j <= 12; j++) c = cmul(c, f[j][(tid >> (j - 8)) & 1]);
        float2 F[8];
        #pragma unroll
        for (int i = 0; i < 8; i++)
            F[i] = cmul(cmul(f[13][i & 1], f[14][(i >> 1) & 1]), f[15][(i >> 2) & 1]);
        float2 cs = g_crx[0][0];                      // q0: ctrl b15 -> tgt b14
        crxmix(F[4], F[6], cs.x, cs.y); crxmix(F[5], F[7], cs.x, cs.y);
        cs = g_crx[0][1];                             // q1: ctrl b14 -> tgt b13
        crxmix(F[2], F[3], cs.x, cs.y); crxmix(F[6], F[7], cs.x, cs.y);
        Bv[tid] = cmul(c, F[chunk]);
    }
    __syncthreads();
    #pragma unroll
    for (int k = 0; k < 32; k++) {
        int j = tid + (k << 8);
        s[PD(j)] = cmul(A[j & 255], Bv[j >> 8]);
    }
    __syncthreads();
    bool doq2 = (chunk & 1);                          // j13 == 1
    window_chain(s, tid,       9, 0, 3, &g_U[1][b][3][0], &g_U[1][b][4][0], &g_U[1][b][5][0], doq2, 2);
    window_chain(s, tid + 256, 9, 0, 3, &g_U[1][b][3][0], &g_U[1][b][4][0], &g_U[1][b][5][0], doq2, 2);
    __syncthreads();
    window_chain(s, tid,       6, 0, 6, &g_U[1][b][6][0], &g_U[1][b][7][0], &g_U[1][b][8][0], false, 0);
    window_chain(s, tid + 256, 6, 0, 6, &g_U[1][b][6][0], &g_U[1][b][7][0], &g_U[1][b][8][0], false, 0);
    __syncthreads();
    window_chain(s, tid,       3, 0, 9, &g_U[1][b][9][0], &g_U[1][b][10][0], &g_U[1][b][11][0], false, 0);
    window_chain(s, tid + 256, 3, 0, 9, &g_U[1][b][9][0], &g_U[1][b][10][0], &g_U[1][b][11][0], false, 0);
    __syncthreads();
    window_chain(s, tid,       0, 0, 12, &g_U[1][b][12][0], &g_U[1][b][13][0], &g_U[1][b][14][0], false, 0);
    window_chain(s, tid + 256, 0, 0, 12, &g_U[1][b][12][0], &g_U[1][b][13][0], &g_U[1][b][14][0], false, 0);
    __syncthreads();
    float4* g4 = g_state4 + (size_t)b * 32768 + (size_t)chunk * 4096;
    #pragma unroll
    for (int k = 0; k < 16; k++) {
        int p = tid + (k << 8);
        float2 lo = s[PD(2 * p)], hi = s[PD(2 * p + 1)];
        g4[p] = make_float4(lo.x, lo.y, hi.x, hi.y);
    }
}

// ------- P2: k_bnd2 — owns j bits {15,14,13,12}; chunk over j[0..11].
// Gates: L1 wrap q15 (cond on b0 = t&1); L2 U wires 0,1,2; L2 CRX q0,q1,q2.
__global__ __launch_bounds__(256, 4) void k_bnd2() {
    int b = blockIdx.y;
    int t = blockIdx.x * blockDim.x + threadIdx.x;   // 0..4095 = j[0..11]
    float2* g2 = (float2*)g_state4 + (size_t)b * DIM;
    float2 r[16];                                    // i = (b15<<3)|(b14<<2)|(b13<<1)|b12
    #pragma unroll
    for (int i = 0; i < 16; i++) r[i] = g2[t | (i << 12)];
    if (t & 1) {                                     // L1 q15: RX on b15 (ctrl b0=1)
        float2 cs = g_crx[0][15];
        #pragma unroll
        for (int i = 0; i < 8; i++) crxmix(r[i], r[i + 8], cs.x, cs.y);
    }
    applyU<3>(r, &g_U[1][b][0][0]);                  // U wire0 @ b15
    applyU<2>(r, &g_U[1][b][1][0]);                  // U wire1 @ b14
    applyU<1>(r, &g_U[1][b][2][0]);                  // U wire2 @ b13
    {   // L2 q0: ctrl b15 -> tgt b14
        float2 cs = g_crx[1][0];
        crxmix(r[8], r[12], cs.x, cs.y);  crxmix(r[9], r[13], cs.x, cs.y);
        crxmix(r[10], r[14], cs.x, cs.y); crxmix(r[11], r[15], cs.x, cs.y);
    }
    {   // L2 q1: ctrl b14 -> tgt b13
        float2 cs = g_crx[1][1];
        crxmix(r[4], r[6], cs.x, cs.y);   crxmix(r[5], r[7], cs.x, cs.y);
        crxmix(r[12], r[14], cs.x, cs.y); crxmix(r[13], r[15], cs.x, cs.y);
    }
    {   // L2 q2: ctrl b13 -> tgt b12
        float2 cs = g_crx[1][2];
        crxmix(r[2], r[3], cs.x, cs.y);   crxmix(r[6], r[7], cs.x, cs.y);
        crxmix(r[10], r[11], cs.x, cs.y); crxmix(r[14], r[15], cs.x, cs.y);
    }
    #pragma unroll
    for (int i = 0; i < 16; i++) g2[t | (i << 12)] = r[i];
}

// ------- P3: k_chain1m — owns j bits {0..11,15}; chunk = j[12..14].
// L2 q3(cond on b12)..q12 via windows; final window {b0,b1,b2,j15}: U15, q13,
// q14, wrap q15 + fused signed |amp|^2 reduction.  No state store.
// Local m: m[0..11] = j[0..11], m12 = j15.
__global__ __launch_bounds__(256) void k_chain1m() {
    extern __shared__ float2 s[];
    int b = blockIdx.y, chunk = blockIdx.x, tid = threadIdx.x;
    const float4* g4 = g_state4 + (size_t)b * 32768;
    #pragma unroll
    for (int k = 0; k < 16; k++) {
        int p = tid + (k << 8);                      // 0..4095 (f4 within block set)
        float4 v = g4[(p & 2047) | (chunk << 11) | ((p >> 11) << 14)];
        s[PD(2 * p)]     = make_float2(v.x, v.y);
        s[PD(2 * p + 1)] = make_float2(v.z, v.w);
    }
    __syncthreads();
    bool doq3 = (chunk & 1);                         // b12 == 1
    window_chain(s, tid,       8, 1, 4, 0, 0, 0, doq3, 3);   // q3(cond),q4,q5,q6
    window_chain(s, tid + 256, 8, 1, 4, 0, 0, 0, doq3, 3);
    __syncthreads();
    window_chain(s, tid,       5, 1, 7, 0, 0, 0, false, 0);  // q7,q8,q9
    window_chain(s, tid + 256, 5, 1, 7, 0, 0, 0, false, 0);
    __syncthreads();
    window_chain(s, tid,       2, 1, 10, 0, 0, 0, false, 0); // q10,q11,q12
    window_chain(s, tid + 256, 2, 1, 10, 0, 0, 0, false, 0);
    __syncthreads();
    // final window: i = (j15<<3)|(b2<<2)|(b1<<1)|b0; free = b3..b11 (9 bits)
    float sums[16];
    #pragma unroll
    for (int w = 0; w < 16; w++) sums[w] = 0.f;
    float Tc = 0.f;
    const float2* gu = &g_U[1][b][15][0];
    float2 u0 = gu[0], u1 = gu[1], u2 = gu[2], u3 = gu[3];
    float2 c13 = g_crx[1][13], c14 = g_crx[1][14], c15 = g_crx[1][15];
    #pragma unroll
    for (int k = 0; k < 2; k++) {
        int v = tid + (k << 8);                      // 0..511
        int base = v << 3;                           // m bits 3..11
        float2 r[16];
        #pragma unroll
        for (int i = 0; i < 16; i++)
            r[i] = s[PD((i & 7) | base | ((i >> 3) << 12))];
        #pragma unroll
        for (int i = 0; i < 16; i += 2)              // U wire15 @ b0
            umix(r[i], r[i + 1], u0, u1, u2, u3);
        // q13: ctrl b2 -> tgt b1
        crxmix(r[4], r[6], c13.x, c13.y);   crxmix(r[5], r[7], c13.x, c13.y);
        crxmix(r[12], r[14], c13.x, c13.y); crxmix(r[13], r[15], c13.x, c13.y);
        // q14: ctrl b1 -> tgt b0
        crxmix(r[2], r[3], c14.x, c14.y);   crxmix(r[6], r[7], c14.x, c14.y);
        crxmix(r[10], r[11], c14.x, c14.y); crxmix(r[14], r[15], c14.x, c14.y);
        // q15 wrap: ctrl b0 -> tgt j15
        crxmix(r[1], r[9], c15.x, c15.y);   crxmix(r[3], r[11], c15.x, c15.y);
        crxmix(r[5], r[13], c15.x, c15.y);  crxmix(r[7], r[15], c15.x, c15.y);
        float p[16];
        #pragma unroll
        for (int i = 0; i < 16; i++) p[i] = r[i].x * r[i].x + r[i].y * r[i].y;
        float T = 0.f;
        #pragma unroll
        for (int i = 0; i < 16; i++) T += p[i];
        float S3 = p[8] + p[9] + p[10] + p[11] + p[12] + p[13] + p[14] + p[15]; // j15=1
        float S2 = p[4] + p[5] + p[6] + p[7] + p[12] + p[13] + p[14] + p[15];   // b2=1
        float S1 = p[2] + p[3] + p[6] + p[7] + p[10] + p[11] + p[14] + p[15];   // b1=1
        float S0 = p[1] + p[3] + p[5] + p[7] + p[9] + p[11] + p[13] + p[15];    // b0=1
        sums[0]  += T - 2.f * S3;                    // wire0  <- j15
        sums[13] += T - 2.f * S2;                    // wire13 <- b2
        sums[14] += T - 2.f * S1;                    // wire14 <- b1
        sums[15] += T - 2.f * S0;                    // wire15 <- b0
        Tc += T;
        #pragma unroll
        for (int w = 4; w <= 12; w++)                // wire w <- b(15-w) = base bit (12-w)
            sums[w] += ((v >> (12 - w)) & 1) ? -T : T;
    }
    sums[1] = (chunk & 4) ? -Tc : Tc;                // wire1 <- b14
    sums[2] = (chunk & 2) ? -Tc : Tc;                // wire2 <- b13
    sums[3] = (chunk & 1) ? -Tc : Tc;                // wire3 <- b12
    __syncthreads();
    float* sf = (float*)s;                           // 256*17 floats << smem
    #pragma unroll
    for (int w = 0; w < 16; w++) sf[tid * 17 + w] = sums[w];
    __syncthreads();
    int wd = tid >> 5, ln = tid & 31;                // 8 warps, 2 wires each
    #pragma unroll
    for (int rep = 0; rep < 2; rep++) {
        int w = wd * 2 + rep;
        float vv = 0.f;
        #pragma unroll
        for (int k = 0; k < 8; k++) vv += sf[(ln + (k << 5)) * 17 + w];
        #pragma unroll
        for (int o = 16; o; o >>= 1) vv += __shfl_xor_sync(0xffffffffu, vv, o);
        if (ln == 0) g_partial[b][chunk][w] = vv;
    }
}

// ---------------- P4: FC + log_softmax --------------------------------------
__global__ void k_head(const float* __restrict__ fc_w, const float* __restrict__ fc_b,
                       float* __restrict__ out) {
    int b = blockIdx.x, lane = threadIdx.x;
    __shared__ float feats[16];
    if (lane < 16) {
        float v = 0.f;
        #pragma unroll
        for (int k = 0; k < 8; k++) v += g_partial[b][k][lane];
        feats[lane] = v;
    }
    __syncthreads();
    float logit = -1e30f;
    if (lane < NC) {
        float v = fc_b[lane];
        #pragma unroll
        for (int w = 0; w < 16; w++) v += feats[w] * fc_w[lane * 16 + w];
        logit = v;
    }
    float m = logit;
    #pragma unroll
    for (int o = 16; o; o >>= 1) m = fmaxf(m, __shfl_xor_sync(0xffffffffu, m, o));
    float e = (lane < NC) ? expf(logit - m) : 0.f;
    #pragma unroll
    for (int o = 16; o; o >>= 1) e += __shfl_xor_sync(0xffffffffu, e, o);
    float lse = m + logf(e);
    if (lane < NC) out[b * NC + lane] = logit - lse;
}

extern "C" void kernel_launch(void* const* d_in, const int* in_sizes, int n_in,
                              void* d_out, int out_size) {
    const float* x    = (const float*)d_in[0];
    const float* w0   = (const float*)d_in[1];
    const float* x0   = (const float*)d_in[2];
    const float* w1   = (const float*)d_in[3];
    const float* x1   = (const float*)d_in[4];
    const float* fc_w = (const float*)d_in[5];
    const float* fc_b = (const float*)d_in[6];
    float* out = (float*)d_out;

    cudaFuncSetAttribute(k_chain0,  cudaFuncAttributeMaxDynamicSharedMemorySize, SMEM_BYTES);
    cudaFuncSetAttribute(k_chain1m, cudaFuncAttributeMaxDynamicSharedMemorySize, SMEM_BYTES);

    k_prep<<<8, 256>>>(x, w0, x0, w1, x1);
    k_chain0<<<dim3(8, BATCH), 256, SMEM_BYTES>>>();
    k_bnd2<<<dim3(16, BATCH), 256>>>();
    k_chain1m<<<dim3(8, BATCH), 256, SMEM_BYTES>>>();
    k_head<<<BATCH, 32>>>(fc_w, fc_b, out);
}